// round 13
// baseline (speedup 1.0000x reference)
#include <cuda_runtime.h>

#define EPSF     1e-8f
#define PSD_EPSF 1e-5f

typedef unsigned long long u64;

constexpr int Bn = 8, Cn = 8, Fn = 257, Tn = 1500;
constexpr int T2  = Tn / 2;          // 750 float2 per (b,f) row
constexpr int T4  = Tn / 4;
constexpr int FT2 = Fn * T2;
constexpr int FT4 = Fn * T4;
constexpr int BF  = Bn * Fn;         // 2056
constexpr int NSLAB = 32;            // F split for the mask-max kernel
constexpr int FSLAB = 9;             // ceil(257/32)
constexpr int TC = 64;               // t-pairs (float2) per stage
constexpr int NSTAGE = (T2 + TC - 1) / TC;   // 12 (last stage 46)
constexpr int NBUF = 4;              // smem buffers (prefetch depth 3)

// Scratch (no allocations allowed)
__device__ __align__(16) float2 g_part_s[NSLAB * Bn * T2];
__device__ __align__(16) float2 g_part_n[NSLAB * Bn * T2];
__device__ __align__(16) float2 g_recip_s[Bn * T2];
__device__ __align__(16) float2 g_recip_n[Bn * T2];

// ---------------- packed f32x2 helpers ----------------
__device__ __forceinline__ u64 fma2(u64 a, u64 b, u64 c) {
    u64 d; asm("fma.rn.f32x2 %0,%1,%2,%3;" : "=l"(d) : "l"(a), "l"(b), "l"(c)); return d;
}
__device__ __forceinline__ u64 mul2(u64 a, u64 b) {
    u64 d; asm("mul.rn.f32x2 %0,%1,%2;" : "=l"(d) : "l"(a), "l"(b)); return d;
}
__device__ __forceinline__ u64 add2(u64 a, u64 b) {
    u64 d; asm("add.rn.f32x2 %0,%1,%2;" : "=l"(d) : "l"(a), "l"(b)); return d;
}
__device__ __forceinline__ u64 neg2(u64 a) { return a ^ 0x8000000080000000ull; }
__device__ __forceinline__ float2 upk(u64 v) {
    float2 f; f.x = __uint_as_float((unsigned)v); f.y = __uint_as_float((unsigned)(v >> 32)); return f;
}
__device__ __forceinline__ float upks(u64 v) { float2 f = upk(v); return f.x + f.y; }
__device__ __forceinline__ u64 lds64(const float2* p) {
    return *reinterpret_cast<const u64*>(p);
}

// ---------------- TMA bulk-copy + mbarrier helpers ----------------
__device__ __forceinline__ unsigned s2u(const void* p) {
    return (unsigned)__cvta_generic_to_shared(p);
}
__device__ __forceinline__ void cpbulk(unsigned dst_smem, const void* src,
                                       unsigned bytes, unsigned mbar) {
    asm volatile(
        "cp.async.bulk.shared::cta.global.mbarrier::complete_tx::bytes [%0], [%1], %2, [%3];"
        :: "r"(dst_smem), "l"(src), "r"(bytes), "r"(mbar) : "memory");
}
__device__ __forceinline__ void mbar_init(unsigned mbar, unsigned cnt) {
    asm volatile("mbarrier.init.shared.b64 [%0], %1;" :: "r"(mbar), "r"(cnt) : "memory");
}
__device__ __forceinline__ void mbar_expect_tx(unsigned mbar, unsigned bytes) {
    asm volatile("mbarrier.arrive.expect_tx.shared.b64 _, [%0], %1;"
                 :: "r"(mbar), "r"(bytes) : "memory");
}
__device__ __forceinline__ void mbar_wait(unsigned mbar, unsigned parity) {
    asm volatile(
        "{\n\t"
        ".reg .pred P1;\n\t"
        "WAIT_LOOP_%=:\n\t"
        "mbarrier.try_wait.parity.acquire.cta.shared::cta.b64 P1, [%0], %1, 0x989680;\n\t"
        "@P1 bra.uni WAIT_DONE_%=;\n\t"
        "bra.uni WAIT_LOOP_%=;\n\t"
        "WAIT_DONE_%=:\n\t"
        "}"
        :: "r"(mbar), "r"(parity) : "memory");
}

// ---------------------------------------------------------------------------
// A1: partial max over an F-slab per (b, t).  float2, high grid parallelism.
// ---------------------------------------------------------------------------
__global__ void mask_partial_kernel(const float* __restrict__ sm,
                                    const float* __restrict__ nm) {
    int b = blockIdx.y, z = blockIdx.z;
    int idx = blockIdx.x * 128 + threadIdx.x;
    if (idx >= T2) return;
    int f0 = z * FSLAB, f1 = min(Fn, f0 + FSLAB);
    const float2* s = (const float2*)sm + (size_t)b * FT2 + (size_t)f0 * T2 + idx;
    const float2* n = (const float2*)nm + (size_t)b * FT2 + (size_t)f0 * T2 + idx;
    float2 ms = make_float2(0.f, 0.f), mn = make_float2(0.f, 0.f);
#pragma unroll 3
    for (int f = f0; f < f1; f++) {
        float2 v = *s; s += T2;
        ms.x = fmaxf(ms.x, fabsf(v.x)); ms.y = fmaxf(ms.y, fabsf(v.y));
        float2 w = *n; n += T2;
        mn.x = fmaxf(mn.x, fabsf(w.x)); mn.y = fmaxf(mn.y, fabsf(w.y));
    }
    g_part_s[(z * Bn + b) * T2 + idx] = ms;
    g_part_n[(z * Bn + b) * T2 + idx] = mn;
}

// ---------------------------------------------------------------------------
// A2: reduce slabs, store 1/(max+eps).
// ---------------------------------------------------------------------------
__global__ void mask_recip_kernel() {
    int b = blockIdx.y;
    int idx = blockIdx.x * 128 + threadIdx.x;
    if (idx >= T2) return;
    float2 ms = make_float2(0.f, 0.f), mn = make_float2(0.f, 0.f);
#pragma unroll
    for (int z = 0; z < NSLAB; z++) {
        float2 v = g_part_s[(z * Bn + b) * T2 + idx];
        ms.x = fmaxf(ms.x, v.x); ms.y = fmaxf(ms.y, v.y);
        float2 w = g_part_n[(z * Bn + b) * T2 + idx];
        mn.x = fmaxf(mn.x, w.x); mn.y = fmaxf(mn.y, w.y);
    }
    g_recip_s[b * T2 + idx] = make_float2(1.f / (ms.x + EPSF), 1.f / (ms.y + EPSF));
    g_recip_n[b * T2 + idx] = make_float2(1.f / (mn.x + EPSF), 1.f / (mn.y + EPSF));
}

// ---------------------------------------------------------------------------
// Per-warp pair assignment (7 off-diagonal + 2 diagonal pairs per warp).
// ---------------------------------------------------------------------------
__device__ __constant__ unsigned char OFFC[4][7] = {
    {0,0,1,2,2,3,4}, {0,0,1,2,3,4,5}, {0,0,1,2,3,4,5}, {0,1,1,1,2,3,6}};
__device__ __constant__ unsigned char OFFD[4][7] = {
    {1,5,4,3,7,7,7}, {2,6,5,4,4,5,6}, {3,7,6,5,5,6,7}, {4,2,3,7,6,6,7}};

#define OFFP(K, C, D) { \
    u64 ar = vr[C], ai = vi[C], br = vr[D], bi = vi[D]; \
    u64 ore = fma2(ai, bi, mul2(ar, br)); \
    u64 oim = fma2(ai, br, neg2(mul2(ar, bi))); \
    oSr[K] = fma2(ms, ore, oSr[K]);  oSi[K] = fma2(ms, oim, oSi[K]); \
    oNr[K] = fma2(mn, ore, oNr[K]);  oNi[K] = fma2(mn, oim, oNi[K]); }

#define DIAGP(K, C) { \
    u64 ar = vr[C], ai = vi[C]; \
    u64 ore = fma2(ai, ai, mul2(ar, ar)); \
    dSr[K] = fma2(ms, ore, dSr[K]);  dNr[K] = fma2(mn, ore, dNr[K]); }

template<int W>
__device__ __forceinline__ void warp_stage(
    int lane, int cnt,
    const float2 (*sX)[TC], const float2 (*sM)[TC],
    u64* oSr, u64* oSi, u64* oNr, u64* oNi, u64* dSr, u64* dNr,
    u64& dsum, u64& dnum)
{
    for (int j = lane; j < cnt; j += 32) {
        u64 vr[8], vi[8];
#pragma unroll
        for (int c = 0; c < 8; c++) { vr[c] = lds64(&sX[c][j]); vi[c] = lds64(&sX[8 + c][j]); }
        u64 ms = mul2(lds64(&sM[0][j]), lds64(&sM[2][j]));
        u64 mn = mul2(lds64(&sM[1][j]), lds64(&sM[3][j]));
        if (W == 0) { dsum = add2(dsum, ms); dnum = add2(dnum, mn); }
        if (W == 0) { OFFP(0,0,1) OFFP(1,0,5) OFFP(2,1,4) OFFP(3,2,3) OFFP(4,2,7) OFFP(5,3,7) OFFP(6,4,7) DIAGP(0,0) DIAGP(1,1) }
        if (W == 1) { OFFP(0,0,2) OFFP(1,0,6) OFFP(2,1,5) OFFP(3,2,4) OFFP(4,3,4) OFFP(5,4,5) OFFP(6,5,6) DIAGP(0,2) DIAGP(1,3) }
        if (W == 2) { OFFP(0,0,3) OFFP(1,0,7) OFFP(2,1,6) OFFP(3,2,5) OFFP(4,3,5) OFFP(5,4,6) OFFP(6,5,7) DIAGP(0,4) DIAGP(1,5) }
        if (W == 3) { OFFP(0,0,4) OFFP(1,1,2) OFFP(2,1,3) OFFP(3,1,7) OFFP(4,2,6) OFFP(5,3,6) OFFP(6,6,7) DIAGP(0,6) DIAGP(1,7) }
    }
}

// ---------------------------------------------------------------------------
// Fused kernel: per (b,f) block — TMA bulk-copy pipeline (depth 3),
// pair-split PSD accumulation, 8x8 complex inverse, weights, apply.
// ---------------------------------------------------------------------------
__global__ __launch_bounds__(128, 4)
void psd_weight_apply_kernel(const float* __restrict__ smk,
                             const float* __restrict__ nmk,
                             const float* __restrict__ cr,
                             const float* __restrict__ ci,
                             float* __restrict__ out) {
    int bf = blockIdx.x;
    int b  = bf / Fn, f = bf % Fn;
    int tid = threadIdx.x, lane = tid & 31, w = tid >> 5;

    const float2* smr = (const float2*)smk + (size_t)bf * T2;
    const float2* nmr = (const float2*)nmk + (size_t)bf * T2;
    const float2* rs  = g_recip_s + (size_t)b * T2;
    const float2* rn  = g_recip_n + (size_t)b * T2;
    const float2* xr0 = (const float2*)cr + (size_t)b * Cn * FT2 + (size_t)f * T2;
    const float2* xi0 = (const float2*)ci + (size_t)b * Cn * FT2 + (size_t)f * T2;

    // sX rows 0-7: real channels, 8-15: imag channels.
    // sM rows: 0=speech mask, 1=noise mask, 2=speech recip, 3=noise recip.
    __shared__ __align__(16) float2 sX[NBUF][16][TC];
    __shared__ __align__(16) float2 sM[NBUF][4][TC];
    __shared__ __align__(8)  u64    mbar[NBUF];
    __shared__ float  fin[146];
    __shared__ float2 Aug[8][16];
    __shared__ float2 Sp[8][8];
    __shared__ float2 wsh[8];

    if (tid == 0) {
#pragma unroll
        for (int s = 0; s < NBUF; s++) mbar_init(s2u(&mbar[s]), 1);
    }
    __syncthreads();

    // Issue one stage: 20 bulk copies (one per row), tracked by the stage mbarrier.
    auto issue_stage = [&](int st) {
        int buf = st & (NBUF - 1);
        int t0  = st * TC;
        unsigned bytes = (unsigned)(min(TC, T2 - t0) * 8);  // per row (mult of 16)
        unsigned mb = s2u(&mbar[buf]);
        mbar_expect_tx(mb, bytes * 20);
#pragma unroll
        for (int c = 0; c < 8; c++)
            cpbulk(s2u(&sX[buf][c][0]), xr0 + (size_t)c * FT2 + t0, bytes, mb);
#pragma unroll
        for (int c = 0; c < 8; c++)
            cpbulk(s2u(&sX[buf][8 + c][0]), xi0 + (size_t)c * FT2 + t0, bytes, mb);
        cpbulk(s2u(&sM[buf][0][0]), smr + t0, bytes, mb);
        cpbulk(s2u(&sM[buf][1][0]), nmr + t0, bytes, mb);
        cpbulk(s2u(&sM[buf][2][0]), rs + t0, bytes, mb);
        cpbulk(s2u(&sM[buf][3][0]), rn + t0, bytes, mb);
    };

    u64 oSr[7], oSi[7], oNr[7], oNi[7], dSr[2], dNr[2];
#pragma unroll
    for (int k = 0; k < 7; k++) { oSr[k] = 0; oSi[k] = 0; oNr[k] = 0; oNi[k] = 0; }
    dSr[0] = dSr[1] = dNr[0] = dNr[1] = 0;
    u64 dsum = 0, dnum = 0;

    if (tid == 0) {
        issue_stage(0); issue_stage(1); issue_stage(2);   // depth-3 prologue
    }

    for (int st = 0; st < NSTAGE; st++) {
        int buf = st & (NBUF - 1);
        int cnt = min(TC, T2 - st * TC);
        // After this sync every warp finished compute(st-1) -> buffer (st+3)%4 free.
        __syncthreads();
        if (tid == 0 && st + NBUF - 1 < NSTAGE) issue_stage(st + NBUF - 1);
        mbar_wait(s2u(&mbar[buf]), (st >> 2) & 1);
        if      (w == 0) warp_stage<0>(lane, cnt, sX[buf], sM[buf], oSr, oSi, oNr, oNi, dSr, dNr, dsum, dnum);
        else if (w == 1) warp_stage<1>(lane, cnt, sX[buf], sM[buf], oSr, oSi, oNr, oNi, dSr, dNr, dsum, dnum);
        else if (w == 2) warp_stage<2>(lane, cnt, sX[buf], sM[buf], oSr, oSi, oNr, oNi, dSr, dNr, dsum, dnum);
        else             warp_stage<3>(lane, cnt, sX[buf], sM[buf], oSr, oSi, oNr, oNi, dSr, dNr, dsum, dnum);
    }

    // Unpack to f32 first (halves shuffle count), then warp tree-reduce.
    float red[32];
#pragma unroll
    for (int k = 0; k < 7; k++) {
        red[k]      = upks(oSr[k]);
        red[7 + k]  = upks(oSi[k]);
        red[14 + k] = upks(oNr[k]);
        red[21 + k] = upks(oNi[k]);
    }
    red[28] = upks(dSr[0]); red[29] = upks(dSr[1]);
    red[30] = upks(dNr[0]); red[31] = upks(dNr[1]);
    float rds = upks(dsum), rdn = upks(dnum);
#pragma unroll
    for (int o = 16; o > 0; o >>= 1) {
#pragma unroll
        for (int k = 0; k < 32; k++) red[k] += __shfl_xor_sync(~0u, red[k], o);
        if (w == 0) {
            rds += __shfl_xor_sync(~0u, rds, o);
            rdn += __shfl_xor_sync(~0u, rdn, o);
        }
    }
    if (lane == 0) {
#pragma unroll
        for (int k = 0; k < 7; k++) {
            int c = OFFC[w][k], d = OFFD[w][k];
            int p = c * 8 - (c * (c - 1)) / 2 + (d - c);
            fin[2 + p]   = red[k];
            fin[38 + p]  = red[7 + k];
            fin[74 + p]  = red[14 + k];
            fin[110 + p] = red[21 + k];
        }
#pragma unroll
        for (int k = 0; k < 2; k++) {
            int c = 2 * w + k;
            int p = c * 8 - (c * (c - 1)) / 2;
            fin[2 + p]   = red[28 + k];
            fin[38 + p]  = 0.f;
            fin[74 + p]  = red[30 + k];
            fin[110 + p] = 0.f;
        }
        if (w == 0) { fin[0] = rds; fin[1] = rdn; }
    }
    __syncthreads();

    // Build Sp (speech PSD) and Aug = [Noise + eps*I | I]
    if (tid < 64) {
        int c = tid >> 3, d = tid & 7;
        float dens = fmaxf(fin[0], PSD_EPSF);
        float denn = fmaxf(fin[1], PSD_EPSF);
        int lo = min(c, d), hi = max(c, d);
        int p  = lo * 8 - (lo * (lo - 1)) / 2 + (hi - lo);
        float sgn = (c <= d) ? 1.f : -1.f;
        float sre = fin[2 + p] / dens;
        float sim = sgn * fin[38 + p] / dens + (PSD_EPSF + EPSF);
        float nre = fin[74 + p] / denn;
        float nim = sgn * fin[110 + p] / denn + (PSD_EPSF + EPSF);
        if (c == d) nre += EPSF;
        Sp[c][d]      = make_float2(sre, sim);
        Aug[c][d]     = make_float2(nre, nim);
        Aug[c][d + 8] = make_float2((c == d) ? 1.f : 0.f, 0.f);
    }
    __syncthreads();

    // Gauss-Jordan inverse + MVDR weights (warp 0)
    if (tid < 32) {
        int i = tid;
        for (int k = 0; k < 8; k++) {
            if (i == k) {
                float2 piv = Aug[k][k];
                float invm = 1.f / (piv.x * piv.x + piv.y * piv.y);
                float pr = piv.x * invm, pi = -piv.y * invm;
#pragma unroll
                for (int j = 0; j < 16; j++) {
                    float2 v = Aug[k][j];
                    Aug[k][j] = make_float2(v.x * pr - v.y * pi, v.x * pi + v.y * pr);
                }
            }
            __syncwarp();
            if (i < 8 && i != k) {
                float2 fc = Aug[i][k];
#pragma unroll
                for (int j = 0; j < 16; j++) {
                    float2 v = Aug[k][j];
                    float2 q = Aug[i][j];
                    Aug[i][j] = make_float2(q.x - (fc.x * v.x - fc.y * v.y),
                                            q.y - (fc.x * v.y + fc.y * v.x));
                }
            }
            __syncwarp();
        }
        if (i < 8) {
            float2 inv[8];
#pragma unroll
            for (int d = 0; d < 8; d++) { inv[d] = Aug[i][8 + d]; inv[d].y += EPSF; }
            float2 trp = make_float2(0.f, 0.f), u = make_float2(0.f, 0.f);
#pragma unroll
            for (int d = 0; d < 8; d++) {
                float2 s1 = Sp[d][i];
                trp.x += inv[d].x * s1.x - inv[d].y * s1.y;
                trp.y += inv[d].x * s1.y + inv[d].y * s1.x;
                float2 s0 = Sp[d][0];
                u.x += inv[d].x * s0.x - inv[d].y * s0.y;
                u.y += inv[d].x * s0.y + inv[d].y * s0.x;
            }
#pragma unroll
            for (int o = 4; o > 0; o >>= 1) {
                trp.x += __shfl_xor_sync(0xFF, trp.x, o);
                trp.y += __shfl_xor_sync(0xFF, trp.y, o);
            }
            trp.x += EPSF;
            float idn = 1.f / (trp.x * trp.x + trp.y * trp.y);
            float wr = (u.x * trp.x + u.y * trp.y) * idn;
            float wi = (u.y * trp.x - u.x * trp.y) * idn;
            wsh[i] = make_float2(wr, -wi);   // conj(weight)
        }
    }
    __syncthreads();

    // Apply weights: out[b,f,t] = sum_c conj(w)_c * cm[b,c,f,t].
    const float4* xr4 = (const float4*)cr + (size_t)b * Cn * FT4 + (size_t)f * T4;
    const float4* xi4 = (const float4*)ci + (size_t)b * Cn * FT4 + (size_t)f * T4;
    float4* outr = (float4*)out + (size_t)bf * T4;
    float4* outi = (float4*)out + (size_t)BF * T4 + (size_t)bf * T4;
    float2 wl[8];
#pragma unroll
    for (int c = 0; c < 8; c++) wl[c] = wsh[c];
    for (int i = tid; i < T4; i += 128) {
        float4 ar = make_float4(0.f, 0.f, 0.f, 0.f);
        float4 ai = make_float4(0.f, 0.f, 0.f, 0.f);
#pragma unroll
        for (int c = 0; c < 8; c++) {
            float4 xr = xr4[(size_t)c * FT4 + i];
            float4 xi = xi4[(size_t)c * FT4 + i];
            float2 wc = wl[c];
            ar.x += wc.x * xr.x - wc.y * xi.x;  ai.x += wc.x * xi.x + wc.y * xr.x;
            ar.y += wc.x * xr.y - wc.y * xi.y;  ai.y += wc.x * xi.y + wc.y * xr.y;
            ar.z += wc.x * xr.z - wc.y * xi.z;  ai.z += wc.x * xi.z + wc.y * xr.z;
            ar.w += wc.x * xr.w - wc.y * xi.w;  ai.w += wc.x * xi.w + wc.y * xr.w;
        }
        outr[i] = ar;
        outi[i] = ai;
    }
}

extern "C" void kernel_launch(void* const* d_in, const int* in_sizes, int n_in,
                              void* d_out, int out_size) {
    const float* sm = (const float*)d_in[0];
    const float* nm = (const float*)d_in[1];
    const float* cr = (const float*)d_in[2];
    const float* ci = (const float*)d_in[3];
    float* out = (float*)d_out;

    dim3 gA((T2 + 127) / 128, Bn, NSLAB);
    mask_partial_kernel<<<gA, 128>>>(sm, nm);

    dim3 gA2((T2 + 127) / 128, Bn);
    mask_recip_kernel<<<gA2, 128>>>();

    psd_weight_apply_kernel<<<BF, 128>>>(sm, nm, cr, ci, out);
}

// round 17
// speedup vs baseline: 1.5778x; 1.5778x over previous
#include <cuda_runtime.h>

#define EPSF     1e-8f
#define PSD_EPSF 1e-5f

typedef unsigned long long u64;

constexpr int Bn = 8, Cn = 8, Fn = 257, Tn = 1500;
constexpr int T2  = Tn / 2;          // 750 float2 per (b,f) row
constexpr int T4  = Tn / 4;
constexpr int FT2 = Fn * T2;
constexpr int FT4 = Fn * T4;
constexpr int BF  = Bn * Fn;         // 2056
constexpr int NSLAB = 32;            // F split for the mask-max kernel
constexpr int FSLAB = 9;             // ceil(257/32)
constexpr int TC = 64;               // t-pairs (float2) per stage
constexpr int NSTAGE = (T2 + TC - 1) / TC;   // 12 (last stage 46)
constexpr int NBUF = 4;              // smem buffers (prefetch depth 3)

// Scratch (no allocations allowed)
__device__ __align__(16) float2 g_part_s[NSLAB * Bn * T2];
__device__ __align__(16) float2 g_part_n[NSLAB * Bn * T2];
__device__ __align__(16) float2 g_recip_s[Bn * T2];
__device__ __align__(16) float2 g_recip_n[Bn * T2];

// ---------------- packed f32x2 helpers ----------------
__device__ __forceinline__ u64 fma2(u64 a, u64 b, u64 c) {
    u64 d; asm("fma.rn.f32x2 %0,%1,%2,%3;" : "=l"(d) : "l"(a), "l"(b), "l"(c)); return d;
}
__device__ __forceinline__ u64 mul2(u64 a, u64 b) {
    u64 d; asm("mul.rn.f32x2 %0,%1,%2;" : "=l"(d) : "l"(a), "l"(b)); return d;
}
__device__ __forceinline__ u64 add2(u64 a, u64 b) {
    u64 d; asm("add.rn.f32x2 %0,%1,%2;" : "=l"(d) : "l"(a), "l"(b)); return d;
}
__device__ __forceinline__ u64 neg2(u64 a) { return a ^ 0x8000000080000000ull; }
__device__ __forceinline__ float2 upk(u64 v) {
    float2 f; f.x = __uint_as_float((unsigned)v); f.y = __uint_as_float((unsigned)(v >> 32)); return f;
}
__device__ __forceinline__ float upks(u64 v) { float2 f = upk(v); return f.x + f.y; }
__device__ __forceinline__ u64 lds64(const float2* p) {
    return *reinterpret_cast<const u64*>(p);
}

// ---------------- cp.async helpers ----------------
__device__ __forceinline__ void cpa16(void* dst_smem, const void* src) {
    unsigned d = (unsigned)__cvta_generic_to_shared(dst_smem);
    asm volatile("cp.async.cg.shared.global [%0], [%1], 16;\n" :: "r"(d), "l"(src));
}
__device__ __forceinline__ void cpa_commit() { asm volatile("cp.async.commit_group;\n"); }
template<int N> __device__ __forceinline__ void cpa_wait() {
    asm volatile("cp.async.wait_group %0;\n" :: "n"(N));
}

// ---------------------------------------------------------------------------
// A1: partial max over an F-slab per (b, t).
// ---------------------------------------------------------------------------
__global__ void mask_partial_kernel(const float* __restrict__ sm,
                                    const float* __restrict__ nm) {
    int b = blockIdx.y, z = blockIdx.z;
    int idx = blockIdx.x * 128 + threadIdx.x;
    if (idx >= T2) return;
    int f0 = z * FSLAB, f1 = min(Fn, f0 + FSLAB);
    const float2* s = (const float2*)sm + (size_t)b * FT2 + (size_t)f0 * T2 + idx;
    const float2* n = (const float2*)nm + (size_t)b * FT2 + (size_t)f0 * T2 + idx;
    float2 ms = make_float2(0.f, 0.f), mn = make_float2(0.f, 0.f);
#pragma unroll 3
    for (int f = f0; f < f1; f++) {
        float2 v = *s; s += T2;
        ms.x = fmaxf(ms.x, fabsf(v.x)); ms.y = fmaxf(ms.y, fabsf(v.y));
        float2 w = *n; n += T2;
        mn.x = fmaxf(mn.x, fabsf(w.x)); mn.y = fmaxf(mn.y, fabsf(w.y));
    }
    g_part_s[(z * Bn + b) * T2 + idx] = ms;
    g_part_n[(z * Bn + b) * T2 + idx] = mn;
}

// ---------------------------------------------------------------------------
// A2: reduce slabs, store 1/(max+eps).
// ---------------------------------------------------------------------------
__global__ void mask_recip_kernel() {
    int b = blockIdx.y;
    int idx = blockIdx.x * 128 + threadIdx.x;
    if (idx >= T2) return;
    float2 ms = make_float2(0.f, 0.f), mn = make_float2(0.f, 0.f);
#pragma unroll
    for (int z = 0; z < NSLAB; z++) {
        float2 v = g_part_s[(z * Bn + b) * T2 + idx];
        ms.x = fmaxf(ms.x, v.x); ms.y = fmaxf(ms.y, v.y);
        float2 w = g_part_n[(z * Bn + b) * T2 + idx];
        mn.x = fmaxf(mn.x, w.x); mn.y = fmaxf(mn.y, w.y);
    }
    g_recip_s[b * T2 + idx] = make_float2(1.f / (ms.x + EPSF), 1.f / (ms.y + EPSF));
    g_recip_n[b * T2 + idx] = make_float2(1.f / (mn.x + EPSF), 1.f / (mn.y + EPSF));
}

// ---------------------------------------------------------------------------
// Channel-group warp split.
//   W0: pairs within {0,1,2,3} (6 off + 4 diag)   loads 8 rows
//   W1: pairs within {4,5,6,7} (6 off + 4 diag)   loads 8 rows
//   W2: cross {0,1} x {4,5,6,7} (8 off)           loads 12 rows
//   W3: cross {2,3} x {4,5,6,7} (8 off)           loads 12 rows
// Packed Hermitian index p(c,d) = c*8 - c(c-1)/2 + (d-c), c<=d.
// ---------------------------------------------------------------------------
__device__ __constant__ unsigned char POFF[4][8] = {
    {1, 2, 3, 9, 10, 16, 0, 0},          // W0: (0,1)(0,2)(0,3)(1,2)(1,3)(2,3)
    {27, 28, 29, 31, 32, 34, 0, 0},      // W1: (4,5)(4,6)(4,7)(5,6)(5,7)(6,7)
    {4, 5, 6, 7, 11, 12, 13, 14},        // W2: (0,4)..(0,7)(1,4)..(1,7)
    {17, 18, 19, 20, 22, 23, 24, 25}};   // W3: (2,4)..(2,7)(3,4)..(3,7)
__device__ __constant__ unsigned char PDIAG[2][4] = {
    {0, 8, 15, 21},      // W0 diag: p(0,0) p(1,1) p(2,2) p(3,3)
    {26, 30, 33, 35}};   // W1 diag: p(4,4)..p(7,7)

// off-pair accumulate: 6 f32x2 ops
#define OFFPAIR(K, AR, AI, BR, BI) { \
    u64 ore = fma2(AI, BI, mul2(AR, BR)); \
    u64 oim = fma2(AI, BR, neg2(mul2(AR, BI))); \
    oSr[K] = fma2(ms, ore, oSr[K]);  oSi[K] = fma2(ms, oim, oSi[K]); \
    oNr[K] = fma2(mn, ore, oNr[K]);  oNi[K] = fma2(mn, oim, oNi[K]); }

// diag accumulate: 3 f32x2 ops
#define DIAGPAIR(K, AR, AI) { \
    u64 ore = fma2(AI, AI, mul2(AR, AR)); \
    dS[K] = fma2(ms, ore, dS[K]);  dN[K] = fma2(mn, ore, dN[K]); }

// Within-group warp: ROWBASE = 0 (W0) or 4 (W1). 6 off + 4 diag.
template<int ROWBASE, bool DSUM>
__device__ __forceinline__ void warp_within(
    int lane, int cnt,
    const float2 (*sX)[TC], const float2 (*sM)[TC],
    u64* oSr, u64* oSi, u64* oNr, u64* oNi, u64* dS, u64* dN,
    u64& dsum, u64& dnum)
{
    for (int j = lane; j < cnt; j += 32) {
        u64 vr[4], vi[4];
#pragma unroll
        for (int c = 0; c < 4; c++) {
            vr[c] = lds64(&sX[ROWBASE + c][j]);
            vi[c] = lds64(&sX[8 + ROWBASE + c][j]);
        }
        u64 ms = mul2(lds64(&sM[0][j]), lds64(&sM[2][j]));
        u64 mn = mul2(lds64(&sM[1][j]), lds64(&sM[3][j]));
        if (DSUM) { dsum = add2(dsum, ms); dnum = add2(dnum, mn); }
        OFFPAIR(0, vr[0], vi[0], vr[1], vi[1])
        OFFPAIR(1, vr[0], vi[0], vr[2], vi[2])
        OFFPAIR(2, vr[0], vi[0], vr[3], vi[3])
        OFFPAIR(3, vr[1], vi[1], vr[2], vi[2])
        OFFPAIR(4, vr[1], vi[1], vr[3], vi[3])
        OFFPAIR(5, vr[2], vi[2], vr[3], vi[3])
        DIAGPAIR(0, vr[0], vi[0])
        DIAGPAIR(1, vr[1], vi[1])
        DIAGPAIR(2, vr[2], vi[2])
        DIAGPAIR(3, vr[3], vi[3])
    }
}

// Cross warp: A-channels {AB, AB+1}, B-channels {4..7}. 8 off pairs.
template<int AB>
__device__ __forceinline__ void warp_cross(
    int lane, int cnt,
    const float2 (*sX)[TC], const float2 (*sM)[TC],
    u64* oSr, u64* oSi, u64* oNr, u64* oNi)
{
    for (int j = lane; j < cnt; j += 32) {
        u64 ar[2], ai[2], br[4], bi[4];
#pragma unroll
        for (int c = 0; c < 2; c++) {
            ar[c] = lds64(&sX[AB + c][j]);
            ai[c] = lds64(&sX[8 + AB + c][j]);
        }
#pragma unroll
        for (int c = 0; c < 4; c++) {
            br[c] = lds64(&sX[4 + c][j]);
            bi[c] = lds64(&sX[12 + c][j]);
        }
        u64 ms = mul2(lds64(&sM[0][j]), lds64(&sM[2][j]));
        u64 mn = mul2(lds64(&sM[1][j]), lds64(&sM[3][j]));
        OFFPAIR(0, ar[0], ai[0], br[0], bi[0])
        OFFPAIR(1, ar[0], ai[0], br[1], bi[1])
        OFFPAIR(2, ar[0], ai[0], br[2], bi[2])
        OFFPAIR(3, ar[0], ai[0], br[3], bi[3])
        OFFPAIR(4, ar[1], ai[1], br[0], bi[0])
        OFFPAIR(5, ar[1], ai[1], br[1], bi[1])
        OFFPAIR(6, ar[1], ai[1], br[2], bi[2])
        OFFPAIR(7, ar[1], ai[1], br[3], bi[3])
    }
}

// ---------------------------------------------------------------------------
// Fused kernel: per (b,f) block — cp.async pipeline (depth 3), channel-group
// PSD accumulation, 8x8 complex inverse, MVDR weights, apply.
// Race-free stage ordering: wait_group -> __syncthreads -> issue -> compute.
// (wait_group is per-thread; the barrier AFTER all threads' waits is what
//  publishes every thread's staged chunks before any warp reads them.)
// ---------------------------------------------------------------------------
__global__ __launch_bounds__(128, 4)
void psd_weight_apply_kernel(const float* __restrict__ smk,
                             const float* __restrict__ nmk,
                             const float* __restrict__ cr,
                             const float* __restrict__ ci,
                             float* __restrict__ out) {
    int bf = blockIdx.x;
    int b  = bf / Fn, f = bf % Fn;
    int tid = threadIdx.x, lane = tid & 31, w = tid >> 5;

    const float2* smr = (const float2*)smk + (size_t)bf * T2;
    const float2* nmr = (const float2*)nmk + (size_t)bf * T2;
    const float2* rs  = g_recip_s + (size_t)b * T2;
    const float2* rn  = g_recip_n + (size_t)b * T2;
    const float2* xr0 = (const float2*)cr + (size_t)b * Cn * FT2 + (size_t)f * T2;
    const float2* xi0 = (const float2*)ci + (size_t)b * Cn * FT2 + (size_t)f * T2;

    // sX rows 0-7: real channels, 8-15: imag channels.
    // sM rows: 0=speech mask, 1=noise mask, 2=speech recip, 3=noise recip.
    __shared__ __align__(16) float2 sX[NBUF][16][TC];
    __shared__ __align__(16) float2 sM[NBUF][4][TC];
    __shared__ float  fin[146];
    __shared__ float2 Aug[8][16];
    __shared__ float2 Sp[8][8];
    __shared__ float2 wsh[8];

    // Issue one stage's cp.async copies (20 rows x up to TC/2 16B chunks).
    auto issue_stage = [&](int buf, int st) {
        int t0 = st * TC;
        int chunks = min(TC, T2 - t0) >> 1;   // 16B chunks (2 float2); 46 -> 23
        for (int i = tid; i < 20 * (TC / 2); i += 128) {
            int row = i / (TC / 2), ch = i - row * (TC / 2);
            if (ch < chunks) {
                const float2* src;
                void* dst;
                if (row < 8)       { src = xr0 + (size_t)row * FT2 + t0 + ch * 2;       dst = &sX[buf][row][ch * 2]; }
                else if (row < 16) { src = xi0 + (size_t)(row - 8) * FT2 + t0 + ch * 2; dst = &sX[buf][row][ch * 2]; }
                else if (row == 16){ src = smr + t0 + ch * 2;                            dst = &sM[buf][0][ch * 2]; }
                else if (row == 17){ src = nmr + t0 + ch * 2;                            dst = &sM[buf][1][ch * 2]; }
                else if (row == 18){ src = rs  + t0 + ch * 2;                            dst = &sM[buf][2][ch * 2]; }
                else               { src = rn  + t0 + ch * 2;                            dst = &sM[buf][3][ch * 2]; }
                cpa16(dst, src);
            }
        }
    };

    // Accumulators: 6 or 8 off-pairs (x4 components) + up to 4 diag (x2).
    u64 oSr[8], oSi[8], oNr[8], oNi[8], dS[4], dN[4];
#pragma unroll
    for (int k = 0; k < 8; k++) { oSr[k] = 0; oSi[k] = 0; oNr[k] = 0; oNi[k] = 0; }
#pragma unroll
    for (int k = 0; k < 4; k++) { dS[k] = 0; dN[k] = 0; }
    u64 dsum = 0, dnum = 0;

    // Prologue: prefetch stages 0..2 (depth 3, 3 committed groups).
#pragma unroll
    for (int s = 0; s < NBUF - 1; s++) {
        issue_stage(s, s);
        cpa_commit();
    }

    for (int st = 0; st < NSTAGE; st++) {
        int buf = st & (NBUF - 1);
        int cnt = min(TC, T2 - st * TC);
        // Commits so far = 3 + st. Waiting to <=2 pending completes groups
        // 0..st for THIS thread -> this thread's stage-st chunks are in smem.
        cpa_wait<NBUF - 2>();
        // Barrier: every thread has drained its stage-st groups -> all chunks
        // of stage st are visible block-wide. Also guarantees compute(st-1)
        // finished, so buf (st-1)&3 is safe to overwrite below.
        __syncthreads();
        if (st + NBUF - 1 < NSTAGE) issue_stage((st + NBUF - 1) & (NBUF - 1), st + NBUF - 1);
        cpa_commit();                 // unconditional: keeps group count aligned
        if      (w == 0) warp_within<0, true >(lane, cnt, sX[buf], sM[buf], oSr, oSi, oNr, oNi, dS, dN, dsum, dnum);
        else if (w == 1) warp_within<4, false>(lane, cnt, sX[buf], sM[buf], oSr, oSi, oNr, oNi, dS, dN, dsum, dnum);
        else if (w == 2) warp_cross<0>(lane, cnt, sX[buf], sM[buf], oSr, oSi, oNr, oNi);
        else             warp_cross<2>(lane, cnt, sX[buf], sM[buf], oSr, oSi, oNr, oNi);
    }

    // Unpack to f32 (halves shuffle count), then warp tree-reduce 32 values.
    float red[32];
    if (w < 2) {
#pragma unroll
        for (int k = 0; k < 6; k++) {
            red[k]      = upks(oSr[k]);
            red[6 + k]  = upks(oSi[k]);
            red[12 + k] = upks(oNr[k]);
            red[18 + k] = upks(oNi[k]);
        }
#pragma unroll
        for (int k = 0; k < 4; k++) {
            red[24 + k] = upks(dS[k]);
            red[28 + k] = upks(dN[k]);
        }
    } else {
#pragma unroll
        for (int k = 0; k < 8; k++) {
            red[k]      = upks(oSr[k]);
            red[8 + k]  = upks(oSi[k]);
            red[16 + k] = upks(oNr[k]);
            red[24 + k] = upks(oNi[k]);
        }
    }
    float rds = upks(dsum), rdn = upks(dnum);
#pragma unroll
    for (int o = 16; o > 0; o >>= 1) {
#pragma unroll
        for (int k = 0; k < 32; k++) red[k] += __shfl_xor_sync(~0u, red[k], o);
        if (w == 0) {
            rds += __shfl_xor_sync(~0u, rds, o);
            rdn += __shfl_xor_sync(~0u, rdn, o);
        }
    }
    if (lane == 0) {
        if (w < 2) {
#pragma unroll
            for (int k = 0; k < 6; k++) {
                int p = POFF[w][k];
                fin[2 + p]   = red[k];
                fin[38 + p]  = red[6 + k];
                fin[74 + p]  = red[12 + k];
                fin[110 + p] = red[18 + k];
            }
#pragma unroll
            for (int k = 0; k < 4; k++) {
                int p = PDIAG[w][k];
                fin[2 + p]   = red[24 + k];
                fin[38 + p]  = 0.f;
                fin[74 + p]  = red[28 + k];
                fin[110 + p] = 0.f;
            }
            if (w == 0) { fin[0] = rds; fin[1] = rdn; }
        } else {
#pragma unroll
            for (int k = 0; k < 8; k++) {
                int p = POFF[w][k];
                fin[2 + p]   = red[k];
                fin[38 + p]  = red[8 + k];
                fin[74 + p]  = red[16 + k];
                fin[110 + p] = red[24 + k];
            }
        }
    }
    __syncthreads();

    // Build Sp (speech PSD) and Aug = [Noise + eps*I | I]
    if (tid < 64) {
        int c = tid >> 3, d = tid & 7;
        float dens = fmaxf(fin[0], PSD_EPSF);
        float denn = fmaxf(fin[1], PSD_EPSF);
        int lo = min(c, d), hi = max(c, d);
        int p  = lo * 8 - (lo * (lo - 1)) / 2 + (hi - lo);
        float sgn = (c <= d) ? 1.f : -1.f;
        float sre = fin[2 + p] / dens;
        float sim = sgn * fin[38 + p] / dens + (PSD_EPSF + EPSF);
        float nre = fin[74 + p] / denn;
        float nim = sgn * fin[110 + p] / denn + (PSD_EPSF + EPSF);
        if (c == d) nre += EPSF;
        Sp[c][d]      = make_float2(sre, sim);
        Aug[c][d]     = make_float2(nre, nim);
        Aug[c][d + 8] = make_float2((c == d) ? 1.f : 0.f, 0.f);
    }
    __syncthreads();

    // Gauss-Jordan inverse + MVDR weights (warp 0)
    if (tid < 32) {
        int i = tid;
        for (int k = 0; k < 8; k++) {
            if (i == k) {
                float2 piv = Aug[k][k];
                float invm = 1.f / (piv.x * piv.x + piv.y * piv.y);
                float pr = piv.x * invm, pi = -piv.y * invm;
#pragma unroll
                for (int j = 0; j < 16; j++) {
                    float2 v = Aug[k][j];
                    Aug[k][j] = make_float2(v.x * pr - v.y * pi, v.x * pi + v.y * pr);
                }
            }
            __syncwarp();
            if (i < 8 && i != k) {
                float2 fc = Aug[i][k];
#pragma unroll
                for (int j = 0; j < 16; j++) {
                    float2 v = Aug[k][j];
                    float2 q = Aug[i][j];
                    Aug[i][j] = make_float2(q.x - (fc.x * v.x - fc.y * v.y),
                                            q.y - (fc.x * v.y + fc.y * v.x));
                }
            }
            __syncwarp();
        }
        if (i < 8) {
            float2 inv[8];
#pragma unroll
            for (int d = 0; d < 8; d++) { inv[d] = Aug[i][8 + d]; inv[d].y += EPSF; }
            float2 trp = make_float2(0.f, 0.f), u = make_float2(0.f, 0.f);
#pragma unroll
            for (int d = 0; d < 8; d++) {
                float2 s1 = Sp[d][i];
                trp.x += inv[d].x * s1.x - inv[d].y * s1.y;
                trp.y += inv[d].x * s1.y + inv[d].y * s1.x;
                float2 s0 = Sp[d][0];
                u.x += inv[d].x * s0.x - inv[d].y * s0.y;
                u.y += inv[d].x * s0.y + inv[d].y * s0.x;
            }
#pragma unroll
            for (int o = 4; o > 0; o >>= 1) {
                trp.x += __shfl_xor_sync(0xFF, trp.x, o);
                trp.y += __shfl_xor_sync(0xFF, trp.y, o);
            }
            trp.x += EPSF;
            float idn = 1.f / (trp.x * trp.x + trp.y * trp.y);
            float wr = (u.x * trp.x + u.y * trp.y) * idn;
            float wi = (u.y * trp.x - u.x * trp.y) * idn;
            wsh[i] = make_float2(wr, -wi);   // conj(weight)
        }
    }
    __syncthreads();

    // Apply weights: out[b,f,t] = sum_c conj(w)_c * cm[b,c,f,t].
    const float4* xr4 = (const float4*)cr + (size_t)b * Cn * FT4 + (size_t)f * T4;
    const float4* xi4 = (const float4*)ci + (size_t)b * Cn * FT4 + (size_t)f * T4;
    float4* outr = (float4*)out + (size_t)bf * T4;
    float4* outi = (float4*)out + (size_t)BF * T4 + (size_t)bf * T4;
    float2 wl[8];
#pragma unroll
    for (int c = 0; c < 8; c++) wl[c] = wsh[c];
    for (int i = tid; i < T4; i += 128) {
        float4 ar = make_float4(0.f, 0.f, 0.f, 0.f);
        float4 ai = make_float4(0.f, 0.f, 0.f, 0.f);
#pragma unroll
        for (int c = 0; c < 8; c++) {
            float4 xr = xr4[(size_t)c * FT4 + i];
            float4 xi = xi4[(size_t)c * FT4 + i];
            float2 wc = wl[c];
            ar.x += wc.x * xr.x - wc.y * xi.x;  ai.x += wc.x * xi.x + wc.y * xr.x;
            ar.y += wc.x * xr.y - wc.y * xi.y;  ai.y += wc.x * xi.y + wc.y * xr.y;
            ar.z += wc.x * xr.z - wc.y * xi.z;  ai.z += wc.x * xi.z + wc.y * xr.z;
            ar.w += wc.x * xr.w - wc.y * xi.w;  ai.w += wc.x * xi.w + wc.y * xr.w;
        }
        outr[i] = ar;
        outi[i] = ai;
    }
}

extern "C" void kernel_launch(void* const* d_in, const int* in_sizes, int n_in,
                              void* d_out, int out_size) {
    const float* sm = (const float*)d_in[0];
    const float* nm = (const float*)d_in[1];
    const float* cr = (const float*)d_in[2];
    const float* ci = (const float*)d_in[3];
    float* out = (float*)d_out;

    dim3 gA((T2 + 127) / 128, Bn, NSLAB);
    mask_partial_kernel<<<gA, 128>>>(sm, nm);

    dim3 gA2((T2 + 127) / 128, Bn);
    mask_recip_kernel<<<gA2, 128>>>();

    psd_weight_apply_kernel<<<BF, 128>>>(sm, nm, cr, ci, out);
}